// round 16
// baseline (speedup 1.0000x reference)
#include <cuda_runtime.h>
#include <cuda_bf16.h>
#include <math.h>
#include <cstdint>

// ---------------- problem constants ----------------
#define BQ      3600
#define QD      256
#define TOT     24576
#define P1SZ    16384
#define OUTIN   16384
#define NSPLIT  16

// ---------------- scratch (device globals) ----------------
__device__ float g_params[(size_t)BQ * TOT];
__device__ float g_part[(size_t)NSPLIT * BQ * QD];
__device__ float g_qf_t[(size_t)BQ * QD];          // tf32-rounded qf
__device__ float g_wgt[(size_t)TOT * QD];          // W_gen^T [N,K] tf32-rounded
__device__ float g_wot[(size_t)QD * OUTIN];        // W_out^T [N,K] tf32-rounded
__device__ float g_out2[(size_t)BQ * OUTIN];       // mixer out, tf32-rounded

// ---------------- PTX helpers ----------------
__device__ __forceinline__ uint32_t smem_u32(const void* p) {
    uint32_t a;
    asm("{ .reg .u64 t; cvta.to.shared.u64 t, %1; cvt.u32.u64 %0, t; }" : "=r"(a) : "l"(p));
    return a;
}
__device__ __forceinline__ void cp_async16(uint32_t dst, const void* src, uint32_t ssize) {
    asm volatile("cp.async.cg.shared.global [%0], [%1], 16, %2;"
                 :: "r"(dst), "l"(src), "r"(ssize) : "memory");
}
#define CP_COMMIT() asm volatile("cp.async.commit_group;" ::: "memory")
#define CP_WAIT(N)  asm volatile("cp.async.wait_group %0;" :: "n"(N) : "memory")

__device__ __forceinline__ void ldsm4(uint32_t* r, uint32_t addr) {
    asm volatile("ldmatrix.sync.aligned.m8n8.x4.shared.b16 {%0,%1,%2,%3}, [%4];"
                 : "=r"(r[0]), "=r"(r[1]), "=r"(r[2]), "=r"(r[3]) : "r"(addr));
}
__device__ __forceinline__ void ldsm4t(uint32_t* r, uint32_t addr) {
    asm volatile("ldmatrix.sync.aligned.m8n8.x4.trans.shared.b16 {%0,%1,%2,%3}, [%4];"
                 : "=r"(r[0]), "=r"(r[1]), "=r"(r[2]), "=r"(r[3]) : "r"(addr));
}
__device__ __forceinline__ void mma_bf16(float* c, const uint32_t* a, const uint32_t* b) {
    asm volatile(
        "mma.sync.aligned.m16n8k16.row.col.f32.bf16.bf16.f32 "
        "{%0,%1,%2,%3}, {%4,%5,%6,%7}, {%8,%9}, {%0,%1,%2,%3};"
        : "+f"(c[0]), "+f"(c[1]), "+f"(c[2]), "+f"(c[3])
        : "r"(a[0]), "r"(a[1]), "r"(a[2]), "r"(a[3]), "r"(b[0]), "r"(b[1]));
}
__device__ __forceinline__ void mma_tf32(float* c, const uint32_t* a, const uint32_t* b) {
    asm volatile(
        "mma.sync.aligned.m16n8k8.row.col.f32.tf32.tf32.f32 "
        "{%0,%1,%2,%3}, {%4,%5,%6,%7}, {%8,%9}, {%0,%1,%2,%3};"
        : "+f"(c[0]), "+f"(c[1]), "+f"(c[2]), "+f"(c[3])
        : "r"(a[0]), "r"(a[1]), "r"(a[2]), "r"(a[3]), "r"(b[0]), "r"(b[1]));
}
__device__ __forceinline__ float to_tf32(float x) {
    uint32_t r;
    asm("cvt.rna.tf32.f32 %0, %1;" : "=r"(r) : "f"(x));
    return __uint_as_float(r);
}

#define SWC(r, c)  ((((c) + (r) + ((r) >> 2)) & 3))   // 64B rows (4 chunks)
#define SW8(r, c)  ((((c) + (r)) & 7))                // 128B rows (8 chunks)

// ---------------- misc helpers ----------------
__device__ __forceinline__ float gelu_exact(float x) {
    return 0.5f * x * (1.0f + erff(x * 0.70710678118654752f));
}
__device__ __forceinline__ uint32_t packbf(__nv_bfloat16 a, __nv_bfloat16 b) {
    uint16_t ua = *(uint16_t*)&a, ub = *(uint16_t*)&b;
    return (uint32_t)ua | ((uint32_t)ub << 16);
}
__device__ __forceinline__ void split4(float4 v, uint2& hi, uint2& lo) {
    __nv_bfloat16 h0 = __float2bfloat16(v.x), h1 = __float2bfloat16(v.y);
    __nv_bfloat16 h2 = __float2bfloat16(v.z), h3 = __float2bfloat16(v.w);
    __nv_bfloat16 l0 = __float2bfloat16(v.x - __bfloat162float(h0));
    __nv_bfloat16 l1 = __float2bfloat16(v.y - __bfloat162float(h1));
    __nv_bfloat16 l2 = __float2bfloat16(v.z - __bfloat162float(h2));
    __nv_bfloat16 l3 = __float2bfloat16(v.w - __bfloat162float(h3));
    hi.x = packbf(h0, h1); hi.y = packbf(h2, h3);
    lo.x = packbf(l0, l1); lo.y = packbf(l2, l3);
}
__device__ __forceinline__ void blockReduce2(float& s, float& q) {
    __shared__ float rs[8], rq[8];
    #pragma unroll
    for (int o = 16; o > 0; o >>= 1) {
        s += __shfl_down_sync(0xffffffffu, s, o);
        q += __shfl_down_sync(0xffffffffu, q, o);
    }
    int w = threadIdx.x >> 5, l = threadIdx.x & 31;
    if (l == 0) { rs[w] = s; rq[w] = q; }
    __syncthreads();
    if (w == 0) {
        float ts = (l < 8) ? rs[l] : 0.f;
        float tq = (l < 8) ? rq[l] : 0.f;
        #pragma unroll
        for (int o = 4; o > 0; o >>= 1) {
            ts += __shfl_down_sync(0xffu, ts, o);
            tq += __shfl_down_sync(0xffu, tq, o);
        }
        if (l == 0) { rs[0] = ts; rq[0] = tq; }
    }
    __syncthreads();
    s = rs[0]; q = rq[0];
    __syncthreads();
}

// ---------------- prep kernels ----------------
__global__ void __launch_bounds__(256)
round_kernel(const float* __restrict__ src, float* __restrict__ dst, int n)
{
    int i = blockIdx.x * 256 + threadIdx.x;
    if (i < n) dst[i] = to_tf32(src[i]);
}

// src[R][C] -> dst[C][R] tf32-rounded
__global__ void __launch_bounds__(256)
transpose_round_kernel(const float* __restrict__ src, float* __restrict__ dst,
                       int R, int C)
{
    __shared__ float tile[32][33];
    int c0 = blockIdx.x * 32, r0 = blockIdx.y * 32;
    int tx = threadIdx.x & 31, ty = threadIdx.x >> 5;
    #pragma unroll
    for (int i = ty; i < 32; i += 8)
        tile[i][tx] = src[(size_t)(r0 + i) * C + c0 + tx];
    __syncthreads();
    #pragma unroll
    for (int i = ty; i < 32; i += 8)
        dst[(size_t)(c0 + i) * R + r0 + tx] = to_tf32(tile[tx][i]);
}

// ---------------- tf32 single-pass GEMM (128x128 tile, 3-stage, 2 CTA/SM) ----------------
// A[M,K] fp32(tf32) K-major; B[N,K] fp32(tf32) K-major. BK=32.
// Stage: A 16KB | B 16KB = 32KB (128B rows, SW8 chunk swizzle).
#define STAGE_BYTES 32768
#define GEMM_NSTAGE 3
#define SMEM_BYTES  (GEMM_NSTAGE * STAGE_BYTES)

__device__ __forceinline__ void load_stage32(
    uint32_t sbase, const float* __restrict__ A, const float* __restrict__ B,
    int m_base, int n_base, int k0, int M, int K, int tid)
{
    #pragma unroll
    for (int i = 0; i < 8; i++) {
        int idx = i * 256 + tid;      // 0..2047
        int arr = idx >> 10;          // 0:A 1:B
        int rc  = idx & 1023;
        int row = rc >> 3;
        int c   = rc & 7;
        uint32_t so = sbase + arr * 16384 + row * 128 + SW8(row, c) * 16;
        const float* src;
        uint32_t sz = 16;
        if (arr == 0) {
            int gm = m_base + row;
            int gr = (gm < M) ? gm : 0;
            if (gm >= M) sz = 0;
            src = A + (size_t)gr * K + k0 + c * 4;
        } else {
            src = B + (size_t)(n_base + row) * K + k0 + c * 4;
        }
        cp_async16(so, src, sz);
    }
}

__global__ void __launch_bounds__(256, 2)
tf32_gemm(const float* __restrict__ A, const float* __restrict__ B,
          const float* __restrict__ bias, float* __restrict__ C,
          int M, int K, int nch, int ldc, size_t czstride)
{
    extern __shared__ char smem_raw[];
    const uint32_t sbase = smem_u32(smem_raw);

    const int tid = threadIdx.x;
    const int wid = tid >> 5;
    const int lane = tid & 31;
    const int warp_m = wid & 1;      // 64-row slab
    const int warp_n = wid >> 1;     // 32-col slab
    const int m_base = blockIdx.y * 128;
    const int n_base = blockIdx.x * 128;
    const int kbeg = blockIdx.z * nch * 32;
    C += (size_t)blockIdx.z * czstride;

    float acc[4][4][4];
    #pragma unroll
    for (int mi = 0; mi < 4; mi++)
        #pragma unroll
        for (int nj = 0; nj < 4; nj++)
            #pragma unroll
            for (int v = 0; v < 4; v++) acc[mi][nj][v] = 0.f;

    load_stage32(sbase, A, B, m_base, n_base, kbeg, M, K, tid);
    CP_COMMIT();
    if (nch > 1)
        load_stage32(sbase + STAGE_BYTES, A, B, m_base, n_base, kbeg + 32, M, K, tid);
    CP_COMMIT();

    for (int ch = 0; ch < nch; ch++) {
        __syncthreads();
        if (ch + 2 < nch)
            load_stage32(sbase + (uint32_t)((ch + 2) % GEMM_NSTAGE) * STAGE_BYTES,
                         A, B, m_base, n_base, kbeg + (ch + 2) * 32, M, K, tid);
        CP_COMMIT();
        CP_WAIT(2);
        __syncthreads();

        const uint32_t st = sbase + (uint32_t)(ch % GEMM_NSTAGE) * STAGE_BYTES;
        const uint32_t sA = st, sB = st + 16384;

        // m16n8k8 tf32 fragments via ldmatrix.b16 (8x8 b16 tile == 8x4 fp32 tile)
        #pragma unroll
        for (int ks = 0; ks < 4; ks++) {
            uint32_t a[4][4], b[2][4];

            const int arow = (lane & 7) + ((lane >> 3) & 1) * 8;  // row-in-tile
            const int achk = 2 * ks + (lane >> 4);                // 16B chunk
            #pragma unroll
            for (int mi = 0; mi < 4; mi++) {
                int row = warp_m * 64 + mi * 16 + arow;
                uint32_t off = (uint32_t)(row * 128 + SW8(row, achk) * 16);
                ldsm4(a[mi], sA + off);
            }
            const int brow = ((lane >> 4) << 3) + (lane & 7);
            const int bchk = 2 * ks + ((lane >> 3) & 1);
            #pragma unroll
            for (int p = 0; p < 2; p++) {
                int row = warp_n * 32 + p * 16 + brow;
                uint32_t off = (uint32_t)(row * 128 + SW8(row, bchk) * 16);
                ldsm4(b[p], sB + off);
            }
            // acc[mi][2p+s] uses b[p][2s..2s+1]; col offset = (2p+s)*8
            #pragma unroll
            for (int mi = 0; mi < 4; mi++)
                #pragma unroll
                for (int nj = 0; nj < 4; nj++)
                    mma_tf32(acc[mi][nj], a[mi], &b[nj >> 1][(nj & 1) * 2]);
        }
    }

    const int er = lane >> 2;
    const int ec = (lane & 3) * 2;
    float2 bv[4];
    if (bias) {
        #pragma unroll
        for (int nj = 0; nj < 4; nj++) {
            int col = n_base + warp_n * 32 + nj * 8 + ec;
            bv[nj] = *reinterpret_cast<const float2*>(bias + col);
        }
    } else {
        #pragma unroll
        for (int nj = 0; nj < 4; nj++) bv[nj] = make_float2(0.f, 0.f);
    }
    #pragma unroll
    for (int mi = 0; mi < 4; mi++) {
        int gm0 = m_base + warp_m * 64 + mi * 16 + er;
        #pragma unroll
        for (int nj = 0; nj < 4; nj++) {
            int col = n_base + warp_n * 32 + nj * 8 + ec;
            if (gm0 < M) {
                float2 v = make_float2(acc[mi][nj][0] + bv[nj].x,
                                       acc[mi][nj][1] + bv[nj].y);
                *reinterpret_cast<float2*>(C + (size_t)gm0 * ldc + col) = v;
            }
            if (gm0 + 8 < M) {
                float2 v = make_float2(acc[mi][nj][2] + bv[nj].x,
                                       acc[mi][nj][3] + bv[nj].y);
                *reinterpret_cast<float2*>(C + (size_t)(gm0 + 8) * ldc + col) = v;
            }
        }
    }
}

// ---------------- HMMA mixer (bf16x3 internally, fp32-tf32 output) ----------------
#define OFF_SHI  0        // s_hi  [32][64]  4KB, 128B rows, SW8
#define OFF_SLO  4096
#define OFF_P1H  8192     // p1_hi [64][64]  8KB (reused: fp32 out staging 16KB)
#define OFF_P1L  16384
#define OFF_P2H  24576    // p2_hi [64][32]  4KB, 64B rows, SWC
#define OFF_P2L  28672
#define OFF_O1H  32768    // o1_hi [32][64]  4KB
#define OFF_O1L  36864
#define MIX_SMEM 40960

__global__ void __launch_bounds__(256)
mixer_hmma(const float* __restrict__ sampled)
{
    const int bq = blockIdx.x, h = blockIdx.y;
    __shared__ __align__(16) char sm[MIX_SMEM];
    const uint32_t sb = smem_u32(sm);
    const int t = threadIdx.x, wid = t >> 5, lane = t & 31;

    {
        const float4* sp = (const float4*)(sampled + ((size_t)bq * 4 + h) * 2048);
        const float* par = g_params + (size_t)bq * TOT;
        const float4* p1p = (const float4*)(par + h * 4096);
        const float4* p2p = (const float4*)(par + P1SZ + h * 2048);

        #pragma unroll
        for (int j = 0; j < 2; j++) {
            int i4 = t + j * 256;
            float4 v = sp[i4];
            int row = i4 >> 4, col = (i4 & 15) * 4;
            uint32_t off = row * 128 + (SW8(row, col >> 3) << 4) + ((col & 7) << 1);
            uint2 hi, lo; split4(v, hi, lo);
            *(uint2*)(sm + OFF_SHI + off) = hi;
            *(uint2*)(sm + OFF_SLO + off) = lo;
        }
        #pragma unroll
        for (int j = 0; j < 4; j++) {
            int i4 = t + j * 256;
            float4 v = p1p[i4];
            int row = i4 >> 4, col = (i4 & 15) * 4;
            uint32_t off = row * 128 + (SW8(row, col >> 3) << 4) + ((col & 7) << 1);
            uint2 hi, lo; split4(v, hi, lo);
            *(uint2*)(sm + OFF_P1H + off) = hi;
            *(uint2*)(sm + OFF_P1L + off) = lo;
        }
        #pragma unroll
        for (int j = 0; j < 2; j++) {
            int i4 = t + j * 256;
            float4 v = p2p[i4];
            int row = i4 >> 3, col = (i4 & 7) * 4;
            uint32_t off = row * 64 + (SWC(row, col >> 3) << 4) + ((col & 7) << 1);
            uint2 hi, lo; split4(v, hi, lo);
            *(uint2*)(sm + OFF_P2H + off) = hi;
            *(uint2*)(sm + OFF_P2L + off) = lo;
        }
    }
    __syncthreads();

    // ---- GEMM-A: out1 = s @ p1 ----
    const int wm = wid & 1, wn = wid >> 1;
    float accA[2][4];
    #pragma unroll
    for (int nj = 0; nj < 2; nj++)
        #pragma unroll
        for (int v = 0; v < 4; v++) accA[nj][v] = 0.f;

    #pragma unroll
    for (int ks = 0; ks < 4; ks++) {
        uint32_t ah[4], al[4];
        {
            int ar = wm * 16 + (lane & 15);
            int ac = ks * 2 + (lane >> 4);
            uint32_t off = ar * 128 + (SW8(ar, ac) << 4);
            ldsm4(ah, sb + OFF_SHI + off);
            ldsm4(al, sb + OFF_SLO + off);
        }
        uint32_t bh[2][2], bl[2][2];
        {
            int grp = lane >> 3;
            int br = ks * 16 + ((grp & 1) << 3) + (lane & 7);
            int bc = wn * 2 + (grp >> 1);
            uint32_t off = br * 128 + (SW8(br, bc) << 4);
            uint32_t tb[4];
            ldsm4t(tb, sb + OFF_P1H + off);
            bh[0][0] = tb[0]; bh[0][1] = tb[1]; bh[1][0] = tb[2]; bh[1][1] = tb[3];
            ldsm4t(tb, sb + OFF_P1L + off);
            bl[0][0] = tb[0]; bl[0][1] = tb[1]; bl[1][0] = tb[2]; bl[1][1] = tb[3];
        }
        #pragma unroll
        for (int nj = 0; nj < 2; nj++) {
            mma_bf16(accA[nj], ah, bh[nj]);
            mma_bf16(accA[nj], ah, bl[nj]);
            mma_bf16(accA[nj], al, bh[nj]);
        }
    }

    float s = 0.f, q = 0.f;
    #pragma unroll
    for (int nj = 0; nj < 2; nj++)
        #pragma unroll
        for (int v = 0; v < 4; v++) {
            float g = gelu_exact(accA[nj][v]);
            accA[nj][v] = g; s += g; q += g * g;
        }
    blockReduce2(s, q);
    {
        float mean = s * (1.f / 2048.f);
        float var  = q * (1.f / 2048.f) - mean * mean;
        float rsig = rsqrtf(var + 1e-5f);
        #pragma unroll
        for (int nj = 0; nj < 2; nj++)
            #pragma unroll
            for (int half = 0; half < 2; half++) {
                int p = wm * 16 + (lane >> 2) + half * 8;
                int d0 = wn * 16 + nj * 8 + ((lane & 3) << 1);
                float x0 = (accA[nj][half * 2 + 0] - mean) * rsig;
                float x1 = (accA[nj][half * 2 + 1] - mean) * rsig;
                __nv_bfloat16 h0 = __float2bfloat16(x0), h1 = __float2bfloat16(x1);
                __nv_bfloat16 l0 = __float2bfloat16(x0 - __bfloat162float(h0));
                __nv_bfloat16 l1 = __float2bfloat16(x1 - __bfloat162float(h1));
                uint32_t off = p * 128 + (SW8(p, d0 >> 3) << 4) + ((d0 & 7) << 1);
                *(uint32_t*)(sm + OFF_O1H + off) = packbf(h0, h1);
                *(uint32_t*)(sm + OFF_O1L + off) = packbf(l0, l1);
            }
    }
    __syncthreads();

    // ---- GEMM-B: out2 = p2 @ out1 ----
    const int wm2 = wid & 3, wn2 = wid >> 2;
    float accB[4][4];
    #pragma unroll
    for (int nj = 0; nj < 4; nj++)
        #pragma unroll
        for (int v = 0; v < 4; v++) accB[nj][v] = 0.f;

    #pragma unroll
    for (int ks = 0; ks < 2; ks++) {
        uint32_t ah[4], al[4];
        {
            int ar = wm2 * 16 + (lane & 15);
            int ac = ks * 2 + (lane >> 4);
            uint32_t off = ar * 64 + (SWC(ar, ac) << 4);
            ldsm4(ah, sb + OFF_P2H + off);
            ldsm4(al, sb + OFF_P2L + off);
        }
        uint32_t bh[4][2], bl[4][2];
        #pragma unroll
        for (int bt = 0; bt < 2; bt++) {
            int grp = lane >> 3;
            int br = ks * 16 + ((grp & 1) << 3) + (lane & 7);
            int bc = wn2 * 4 + bt * 2 + (grp >> 1);
            uint32_t off = br * 128 + (SW8(br, bc) << 4);
            uint32_t tb[4];
            ldsm4t(tb, sb + OFF_O1H + off);
            bh[bt * 2][0] = tb[0]; bh[bt * 2][1] = tb[1];
            bh[bt * 2 + 1][0] = tb[2]; bh[bt * 2 + 1][1] = tb[3];
            ldsm4t(tb, sb + OFF_O1L + off);
            bl[bt * 2][0] = tb[0]; bl[bt * 2][1] = tb[1];
            bl[bt * 2 + 1][0] = tb[2]; bl[bt * 2 + 1][1] = tb[3];
        }
        #pragma unroll
        for (int nj = 0; nj < 4; nj++) {
            mma_bf16(accB[nj], ah, bh[nj]);
            mma_bf16(accB[nj], ah, bl[nj]);
            mma_bf16(accB[nj], al, bh[nj]);
        }
    }

    s = 0.f; q = 0.f;
    #pragma unroll
    for (int nj = 0; nj < 4; nj++)
        #pragma unroll
        for (int v = 0; v < 4; v++) {
            float g = gelu_exact(accB[nj][v]);
            accB[nj][v] = g; s += g; q += g * g;
        }
    blockReduce2(s, q);
    {
        float mean = s * (1.f / 4096.f);
        float var  = q * (1.f / 4096.f) - mean * mean;
        float rsig = rsqrtf(var + 1e-5f);
        // stage fp32 (tf32-rounded) into P1H..P1L region (16KB, p1 dead now)
        float* stg = (float*)(sm + OFF_P1H);
        #pragma unroll
        for (int nj = 0; nj < 4; nj++)
            #pragma unroll
            for (int half = 0; half < 2; half++) {
                int e = wm2 * 16 + (lane >> 2) + half * 8;
                int d0 = wn2 * 32 + nj * 8 + ((lane & 3) << 1);
                stg[e * 64 + d0]     = to_tf32((accB[nj][half * 2 + 0] - mean) * rsig);
                stg[e * 64 + d0 + 1] = to_tf32((accB[nj][half * 2 + 1] - mean) * rsig);
            }
    }
    __syncthreads();

    {
        float4* src = (float4*)(sm + OFF_P1H);
        float4* dst = (float4*)(g_out2 + (size_t)bq * OUTIN + h * 4096);
        #pragma unroll
        for (int j = 0; j < 4; j++) {
            int i = t + j * 256;
            dst[i] = src[i];
        }
    }
}

// ---------------- split-K reduce + bias + final affine LN ----------------
__global__ void __launch_bounds__(256)
reduce_ln_kernel(const float* __restrict__ b_out,
                 const float* __restrict__ ln_w, const float* __restrict__ ln_b,
                 float* __restrict__ out)
{
    const int r = blockIdx.x;
    const int t = threadIdx.x;
    float x = b_out[t];
    #pragma unroll
    for (int z = 0; z < NSPLIT; z++)
        x += g_part[(size_t)z * BQ * QD + (size_t)r * QD + t];
    float s = x, q = x * x;
    blockReduce2(s, q);
    float mean = s * (1.f / 256.f);
    float var  = q * (1.f / 256.f) - mean * mean;
    float rsig = rsqrtf(var + 1e-5f);
    out[(size_t)r * QD + t] = (x - mean) * rsig * ln_w[t] + ln_b[t];
}

// ---------------- launch ----------------
extern "C" void kernel_launch(void* const* d_in, const int* in_sizes, int n_in,
                              void* d_out, int out_size)
{
    const float* qf = (const float*)d_in[0];
    const float* sf = (const float*)d_in[1];
    const float* Wg = (const float*)d_in[2];
    const float* bg = (const float*)d_in[3];
    const float* Wo = (const float*)d_in[4];
    const float* bo = (const float*)d_in[5];
    const float* lw = (const float*)d_in[6];
    const float* lb = (const float*)d_in[7];
    float* out = (float*)d_out;

    cudaFuncSetAttribute(tf32_gemm, cudaFuncAttributeMaxDynamicSharedMemorySize, SMEM_BYTES);

    float *params_p, *part_p, *qft, *wgt, *wot, *o2;
    cudaGetSymbolAddress((void**)&params_p, g_params);
    cudaGetSymbolAddress((void**)&part_p, g_part);
    cudaGetSymbolAddress((void**)&qft, g_qf_t);
    cudaGetSymbolAddress((void**)&wgt, g_wgt);
    cudaGetSymbolAddress((void**)&wot, g_wot);
    cudaGetSymbolAddress((void**)&o2, g_out2);

    // prep: tf32-round qf; transpose+round W_gen, W_out
    round_kernel<<<(BQ * QD + 255) / 256, 256>>>(qf, qft, BQ * QD);
    transpose_round_kernel<<<dim3(TOT / 32, QD / 32), 256>>>(Wg, wgt, QD, TOT);
    transpose_round_kernel<<<dim3(QD / 32, OUTIN / 32), 256>>>(Wo, wot, OUTIN, QD);

    // GEMM1: params = qf @ W_gen + b_gen   (3600 x 24576 x 256), nch=8
    tf32_gemm<<<dim3(TOT / 128, (BQ + 127) / 128, 1), 256, SMEM_BYTES>>>(
        qft, wgt, bg, params_p, BQ, QD, QD / 32, TOT, 0);

    // fused mixers (HMMA bf16x3 inside; tf32-rounded fp32 out)
    mixer_hmma<<<dim3(BQ, 4), 256>>>(sf);

    // GEMM3 split-K=16: out2 @ W_out partials (3600 x 256 x 16384), nch=32
    tf32_gemm<<<dim3(QD / 128, (BQ + 127) / 128, NSPLIT), 256, SMEM_BYTES>>>(
        o2, wot, nullptr, part_p, BQ, OUTIN, (OUTIN / NSPLIT) / 32,
        QD, (size_t)BQ * QD);

    // reduce + final LN
    reduce_ln_kernel<<<BQ, 256>>>(bo, lw, lb, out);
}